// round 15
// baseline (speedup 1.0000x reference)
#include <cuda_runtime.h>
#include <cuda_fp16.h>
#include <math_constants.h>
#include <cstdint>

// Problem constants
#define NB   4
#define NN   2048
#define NDIM 512
#define NH   8
#define NDH  64
#define NTOK 8192
#define QKVN 1536
#define KSCALE 0.18033688011112042f   // 0.125 * log2(e), folded into Q
#define NSPLIT 2
#define MSPL (NN / NSPLIT)            // 1024 m-columns per split

// Scratch (allocation-free rule: __device__ globals)
__device__ __half g_xh[(size_t)NTOK * NDIM];
__device__ __half g_qkvh[(size_t)NTOK * QKVN];
__device__ __half g_wtqh[(size_t)QKVN * NDIM];
__device__ __half g_wtoh[(size_t)NDIM * NDIM];
__device__ float  g_po[(size_t)NSPLIT * NTOK * NDIM];   // partial O (unnormalized)
__device__ float  g_ps[(size_t)NSPLIT * NTOK * NH];     // partial row sums

// ============================================================================
// helpers
// ============================================================================
__device__ __forceinline__ uint32_t smem_u32(const void* p) {
    uint32_t a;
    asm("{ .reg .u64 t; cvta.to.shared.u64 t, %1; cvt.u32.u64 %0, t; }" : "=r"(a) : "l"(p));
    return a;
}
__device__ __forceinline__ uint32_t h2pack(float lo, float hi) {
    uint32_t r;
    asm("cvt.rn.f16x2.f32 %0, %1, %2;" : "=r"(r) : "f"(hi), "f"(lo));
    return r;
}
__device__ __forceinline__ uint32_t ex2h2(uint32_t x) {
    uint32_t r;
    asm("ex2.approx.f16x2 %0, %1;" : "=r"(r) : "r"(x));
    return r;
}

#define LDSM_X4(r0, r1, r2, r3, addr) \
    asm volatile("ldmatrix.sync.aligned.m8n8.x4.shared.b16 {%0,%1,%2,%3}, [%4];" \
                 : "=r"(r0), "=r"(r1), "=r"(r2), "=r"(r3) : "r"(addr))
#define LDSM_X4T(r0, r1, r2, r3, addr) \
    asm volatile("ldmatrix.sync.aligned.m8n8.x4.trans.shared.b16 {%0,%1,%2,%3}, [%4];" \
                 : "=r"(r0), "=r"(r1), "=r"(r2), "=r"(r3) : "r"(addr))

#define MMA_F16(c, a, bb0, bb1) \
    asm volatile("mma.sync.aligned.m16n8k16.row.col.f32.f16.f16.f32 " \
                 "{%0,%1,%2,%3}, {%4,%5,%6,%7}, {%8,%9}, {%0,%1,%2,%3};" \
                 : "+f"((c)[0]), "+f"((c)[1]), "+f"((c)[2]), "+f"((c)[3]) \
                 : "r"((a)[0]), "r"((a)[1]), "r"((a)[2]), "r"((a)[3]), "r"(bb0), "r"(bb1))

#define STS128(addr, v0, v1, v2, v3) \
    asm volatile("st.shared.v4.b32 [%0], {%1,%2,%3,%4};" \
                 :: "r"(addr), "r"(v0), "r"(v1), "r"(v2), "r"(v3) : "memory")

#define CP_ASYNC16(dst, src) \
    asm volatile("cp.async.cg.shared.global [%0], [%1], 16;" :: "r"(dst), "l"(src))
#define CP_COMMIT() asm volatile("cp.async.commit_group;" ::: "memory")
#define CP_WAIT0()  asm volatile("cp.async.wait_group 0;" ::: "memory")
#define CP_WAIT1()  asm volatile("cp.async.wait_group 1;" ::: "memory")

// ============================================================================
// prepasses
// ============================================================================
__global__ void tohalf(const float* __restrict__ S, __half* __restrict__ D)
{
    const int i = blockIdx.x * blockDim.x + threadIdx.x;
    float4 v = ((const float4*)S)[i];
    ((uint2*)D)[i] = make_uint2(h2pack(v.x, v.y), h2pack(v.z, v.w));
}

__global__ void ktrans_h(const float* __restrict__ S, __half* __restrict__ D, int R, int Cc)
{
    __shared__ float t[32][33];
    const int c0 = blockIdx.x * 32, r0 = blockIdx.y * 32;
    for (int i = threadIdx.y; i < 32; i += 8)
        t[i][threadIdx.x] = S[(size_t)(r0 + i) * Cc + c0 + threadIdx.x];
    __syncthreads();
    for (int i = threadIdx.y; i < 32; i += 8)
        D[(size_t)(c0 + i) * R + r0 + threadIdx.x] = __float2half_rn(t[threadIdx.x][i]);
}

// ============================================================================
// fp16 mma GEMM (R8 best config): C[M,N] = A[M,K] @ Bt[N,K]^T -> half,
// Q region scaled. 128x128x64 tiles, 256 thr, 8 warps (4m x 2n),
// warp tile 32x64, 3-stage cp.async pipeline.
// ============================================================================
#define HSTR 72
#define HBUF (128 * HSTR)
#define GSTG (HBUF * 2)                   // 18432 bytes / operand-stage
#define GSMEM_H (6 * GSTG)                // 110592 bytes

__global__ __launch_bounds__(256) void gemm_h(
    const __half* __restrict__ A, const __half* __restrict__ Bt,
    __half* __restrict__ C, int Nfull, int K)
{
    extern __shared__ __half gs[];
    const int tid = threadIdx.x, lane = tid & 31, wid = tid >> 5;
    const int wm = (wid & 3) * 32, wn = (wid >> 2) * 64;
    const int row0 = blockIdx.y * 128, col0 = blockIdx.x * 128;
    const uint32_t sb = smem_u32(gs);

    const int lrow = lane & 15, lko = (lane >> 4) * 8;
    const uint32_t offA = (uint32_t)(((wm + lrow) * HSTR + lko) * 2);
    const uint32_t offB = (uint32_t)(((wn + lrow) * HSTR + lko) * 2);

    float c[2][8][4];
    #pragma unroll
    for (int i = 0; i < 2; i++)
        #pragma unroll
        for (int j = 0; j < 8; j++)
            #pragma unroll
            for (int q = 0; q < 4; q++) c[i][j][q] = 0.f;

    const int grow = tid >> 1, gc8 = (tid & 1) * 4;
    const __half* Ag = A + (size_t)(row0 + grow) * K + gc8 * 8;
    const __half* Bg = Bt + (size_t)(col0 + grow) * K + gc8 * 8;
    const uint32_t dA = sb + (uint32_t)((grow * HSTR + gc8 * 8) * 2);
    const uint32_t dB = sb + 3 * GSTG + (uint32_t)((grow * HSTR + gc8 * 8) * 2);

    const int KT = K / 64;
    #pragma unroll
    for (int pf = 0; pf < 2; pf++) {
        #pragma unroll
        for (int i = 0; i < 4; i++) {
            CP_ASYNC16(dA + pf * GSTG + i * 16, Ag + pf * 64 + i * 8);
            CP_ASYNC16(dB + pf * GSTG + i * 16, Bg + pf * 64 + i * 8);
        }
        CP_COMMIT();
    }

    for (int kt = 0; kt < KT; kt++) {
        if (kt + 1 < KT) CP_WAIT1(); else CP_WAIT0();
        __syncthreads();
        if (kt + 2 < KT) {
            const int st = (kt + 2) % 3;
            #pragma unroll
            for (int i = 0; i < 4; i++) {
                CP_ASYNC16(dA + st * GSTG + i * 16, Ag + (kt + 2) * 64 + i * 8);
                CP_ASYNC16(dB + st * GSTG + i * 16, Bg + (kt + 2) * 64 + i * 8);
            }
            CP_COMMIT();
        }
        const uint32_t aBase = sb + (kt % 3) * GSTG;
        const uint32_t bBase = sb + 3 * GSTG + (kt % 3) * GSTG;
        #pragma unroll
        for (int k0 = 0; k0 < 64; k0 += 16) {
            uint32_t a[2][4];
            #pragma unroll
            for (int mt = 0; mt < 2; mt++)
                LDSM_X4(a[mt][0], a[mt][1], a[mt][2], a[mt][3],
                        aBase + offA + mt * 16 * HSTR * 2 + k0 * 2);
            #pragma unroll
            for (int nt2 = 0; nt2 < 4; nt2++) {
                uint32_t r0, r1, r2, r3;
                LDSM_X4(r0, r1, r2, r3, bBase + offB + nt2 * 16 * HSTR * 2 + k0 * 2);
                MMA_F16(c[0][2 * nt2],     a[0], r0, r2);
                MMA_F16(c[0][2 * nt2 + 1], a[0], r1, r3);
                MMA_F16(c[1][2 * nt2],     a[1], r0, r2);
                MMA_F16(c[1][2 * nt2 + 1], a[1], r1, r3);
            }
        }
    }

    const int r0l = lane >> 2, q2 = (lane & 3) * 2;
    const float sc = (col0 < NDIM) ? KSCALE : 1.0f;   // scale Q region
    #pragma unroll
    for (int mt = 0; mt < 2; mt++)
        #pragma unroll
        for (int nt = 0; nt < 8; nt++) {
            const int row = row0 + wm + mt * 16 + r0l;
            const int col = col0 + wn + nt * 8 + q2;
            *(uint32_t*)(C + (size_t)row * Nfull + col) =
                h2pack(c[mt][nt][0] * sc, c[mt][nt][1] * sc);
            *(uint32_t*)(C + (size_t)(row + 8) * Nfull + col) =
                h2pack(c[mt][nt][2] * sc, c[mt][nt][3] * sc);
        }
}

// ============================================================================
// Out-projection GEMM with FUSED split-combine on the A operand:
//   A[r][c] = (po0[r][c] + po1[r][c]) / (ps0[r][h] + ps1[r][h])  (half)
// A filled by LDG->normalize->STS (2 k-tiles ahead); B stays cp.async.
// Same tile/warp config as gemm_h. Output f32 + bias.
// ============================================================================
__global__ __launch_bounds__(256) void gemm_fuse(
    const __half* __restrict__ Bt, float* __restrict__ C,
    const float* __restrict__ bias)
{
    extern __shared__ __half gs[];
    const int tid = threadIdx.x, lane = tid & 31, wid = tid >> 5;
    const int wm = (wid & 3) * 32, wn = (wid >> 2) * 64;
    const int row0 = blockIdx.y * 128, col0 = blockIdx.x * 128;
    const uint32_t sb = smem_u32(gs);
    const int K = NDIM, Nfull = NDIM;

    const int lrow = lane & 15, lko = (lane >> 4) * 8;
    const uint32_t offA = (uint32_t)(((wm + lrow) * HSTR + lko) * 2);
    const uint32_t offB = (uint32_t)(((wn + lrow) * HSTR + lko) * 2);

    float c[2][8][4];
    #pragma unroll
    for (int i = 0; i < 2; i++)
        #pragma unroll
        for (int j = 0; j < 8; j++)
            #pragma unroll
            for (int q = 0; q < 4; q++) c[i][j][q] = 0.f;

    // fill mapping: thread -> row grow, 32-col half (ah)
    const int grow = tid >> 1, ah = tid & 1;
    const int r = row0 + grow;                        // global token
    const float* p0 = g_po + (size_t)r * NDIM;
    const float* p1 = p0 + (size_t)NTOK * NDIM;
    const float* s0 = g_ps + (size_t)r * NH;
    const float* s1 = s0 + (size_t)NTOK * NH;
    const uint32_t dAr = sb + (uint32_t)((grow * HSTR + ah * 32) * 2);
    const __half* Bg = Bt + (size_t)(col0 + grow) * K + (tid & 1) * 32;
    const uint32_t dB = sb + 3 * GSTG + (uint32_t)((grow * HSTR + (tid & 1) * 32) * 2);

    // A-fill for one k-tile into stage st (normalize + cvt + STS)
    auto fillA = [&](int kt2, int st) {
        const int c0 = kt2 * 64 + ah * 32;
        const int h = c0 >> 6;
        const float inv = __fdividef(1.f, s0[h] + s1[h]);
        const float4* q0 = (const float4*)(p0 + c0);
        const float4* q1 = (const float4*)(p1 + c0);
        const uint32_t dst = dAr + st * GSTG;
        #pragma unroll 2
        for (int i = 0; i < 8; i += 2) {
            float4 a0 = q0[i],     b0 = q1[i];
            float4 a1 = q0[i + 1], b1 = q1[i + 1];
            a0.x = (a0.x + b0.x) * inv; a0.y = (a0.y + b0.y) * inv;
            a0.z = (a0.z + b0.z) * inv; a0.w = (a0.w + b0.w) * inv;
            a1.x = (a1.x + b1.x) * inv; a1.y = (a1.y + b1.y) * inv;
            a1.z = (a1.z + b1.z) * inv; a1.w = (a1.w + b1.w) * inv;
            STS128(dst + i * 8,
                   h2pack(a0.x, a0.y), h2pack(a0.z, a0.w),
                   h2pack(a1.x, a1.y), h2pack(a1.z, a1.w));
        }
    };

    const int KT = K / 64;   // 8
    #pragma unroll
    for (int pf = 0; pf < 2; pf++) {
        fillA(pf, pf);
        #pragma unroll
        for (int i = 0; i < 4; i++)
            CP_ASYNC16(dB + pf * GSTG + i * 16, Bg + pf * 64 + i * 8);
        CP_COMMIT();
    }

    for (int kt = 0; kt < KT; kt++) {
        if (kt + 1 < KT) CP_WAIT1(); else CP_WAIT0();
        __syncthreads();
        if (kt + 2 < KT) {
            const int st = (kt + 2) % 3;
            fillA(kt + 2, st);
            #pragma unroll
            for (int i = 0; i < 4; i++)
                CP_ASYNC16(dB + st * GSTG + i * 16, Bg + (kt + 2) * 64 + i * 8);
            CP_COMMIT();
        }
        const uint32_t aBase = sb + (kt % 3) * GSTG;
        const uint32_t bBase = sb + 3 * GSTG + (kt % 3) * GSTG;
        #pragma unroll
        for (int k0 = 0; k0 < 64; k0 += 16) {
            uint32_t a[2][4];
            #pragma unroll
            for (int mt = 0; mt < 2; mt++)
                LDSM_X4(a[mt][0], a[mt][1], a[mt][2], a[mt][3],
                        aBase + offA + mt * 16 * HSTR * 2 + k0 * 2);
            #pragma unroll
            for (int nt2 = 0; nt2 < 4; nt2++) {
                uint32_t r0, r1, r2, r3;
                LDSM_X4(r0, r1, r2, r3, bBase + offB + nt2 * 16 * HSTR * 2 + k0 * 2);
                MMA_F16(c[0][2 * nt2],     a[0], r0, r2);
                MMA_F16(c[0][2 * nt2 + 1], a[0], r1, r3);
                MMA_F16(c[1][2 * nt2],     a[1], r0, r2);
                MMA_F16(c[1][2 * nt2 + 1], a[1], r1, r3);
            }
        }
    }

    const int r0l = lane >> 2, q2 = (lane & 3) * 2;
    #pragma unroll
    for (int mt = 0; mt < 2; mt++)
        #pragma unroll
        for (int nt = 0; nt < 8; nt++) {
            const int row = row0 + wm + mt * 16 + r0l;
            const int col = col0 + wn + nt * 8 + q2;
            float2 bb = *(const float2*)(bias + col);
            *(float2*)(C + (size_t)row * Nfull + col) =
                make_float2(c[mt][nt][0] + bb.x, c[mt][nt][1] + bb.y);
            *(float2*)(C + (size_t)(row + 8) * Nfull + col) =
                make_float2(c[mt][nt][2] + bb.x, c[mt][nt][3] + bb.y);
        }
}

// ============================================================================
// fp16 mma flash attention, SPLIT-M (2 splits): each CTA handles a 1024-wide
// m-slice (16 iterations), writes unnormalized fp32 partial O + rowsums.
// CTA: 128 thr (4 warps x 32-row bands), 128 n-rows. ex2.approx.f16x2
// softmax, ones-column MMA row sums. 3-stage Q/V cp.async pipeline.
// smem halves: Ks[128][72] | Qs[3][64][72] | Vs[3][64][72]  (73728 bytes)
// ============================================================================
#define KS_H 0
#define QS_H 9216
#define QVBUF 4608
#define VS_H (QS_H + 3 * QVBUF)
#define ATT_SMEM ((VS_H + 3 * QVBUF) * 2)
#define NTS (MSPL / 64)                   // 16 iterations per split
#define ONES_H2 0x3C003C00u

__global__ __launch_bounds__(128, 3) void attn_h()
{
    extern __shared__ __half sh[];
    const int tid = threadIdx.x, lane = tid & 31, wid = tid >> 5;
    const int bh = blockIdx.y, b = bh >> 3, h = bh & 7;
    const int n0 = blockIdx.x * 128;
    const int m0b = blockIdx.z * MSPL;
    const size_t tb = (size_t)b * NN;
    const int qoff = h * 64, koff = NDIM + h * 64, voff = 2 * NDIM + h * 64;
    const uint32_t sb = smem_u32(sh);

    // K band: one row per thread (128 threads), 8x16B chunks (group 0)
    {
        const __half* src = g_qkvh + (tb + n0 + tid) * QKVN + koff;
        const uint32_t dst = sb + (uint32_t)((KS_H + tid * HSTR) * 2);
        #pragma unroll
        for (int i = 0; i < 8; i++)
            CP_ASYNC16(dst + i * 16, src + i * 8);
    }
    // Q/V tiles 0,1 of this split (2 threads per row, 4 chunks each)
    const int qr = tid >> 1, qc8 = (tid & 1) * 4;
    #pragma unroll
    for (int pf = 0; pf < 2; pf++) {
        const size_t rb = tb + m0b + pf * 64 + qr;
        #pragma unroll
        for (int i = 0; i < 4; i++) {
            CP_ASYNC16(sb + (uint32_t)((QS_H + pf * QVBUF + qr * HSTR + (qc8 + i) * 8) * 2),
                       g_qkvh + rb * QKVN + qoff + (qc8 + i) * 8);
            CP_ASYNC16(sb + (uint32_t)((VS_H + pf * QVBUF + qr * HSTR + (qc8 + i) * 8) * 2),
                       g_qkvh + rb * QKVN + voff + (qc8 + i) * 8);
        }
        CP_COMMIT();
    }

    float o[2][8][4];
    #pragma unroll
    for (int m = 0; m < 2; m++)
        #pragma unroll
        for (int j = 0; j < 8; j++)
            #pragma unroll
            for (int q = 0; q < 4; q++) o[m][j][q] = 0.f;
    float osum[2][4];
    #pragma unroll
    for (int m = 0; m < 2; m++)
        #pragma unroll
        for (int q = 0; q < 4; q++) osum[m][q] = 0.f;

    const int lrow = lane & 15, lko = (lane >> 4) * 8;
    const uint32_t aK0 = sb + (uint32_t)(((wid * 32 + lrow) * HSTR + lko) * 2);
    const uint32_t aK1 = aK0 + 16 * HSTR * 2;
    const int vrow = ((lane >> 3) & 1) * 8 + (lane & 7);
    const int pr = lane >> 2, pc = (lane & 3) * 2;

    for (int it = 0; it < NTS; it++) {
        if (it + 1 < NTS) CP_WAIT1(); else CP_WAIT0();
        __syncthreads();
        if (it + 2 < NTS) {
            const int st = (it + 2) % 3;
            const size_t rb = tb + m0b + (it + 2) * 64 + qr;
            #pragma unroll
            for (int i = 0; i < 4; i++) {
                CP_ASYNC16(sb + (uint32_t)((QS_H + st * QVBUF + qr * HSTR + (qc8 + i) * 8) * 2),
                           g_qkvh + rb * QKVN + qoff + (qc8 + i) * 8);
                CP_ASYNC16(sb + (uint32_t)((VS_H + st * QVBUF + qr * HSTR + (qc8 + i) * 8) * 2),
                           g_qkvh + rb * QKVN + voff + (qc8 + i) * 8);
            }
            CP_COMMIT();
        }
        const int rs = it % 3;
        const uint32_t qb = sb + (uint32_t)((QS_H + rs * QVBUF + lrow * HSTR + lko) * 2);
        const uint32_t vb = sb + (uint32_t)((VS_H + rs * QVBUF + vrow * HSTR + lko) * 2);

        // ---- S = K . Q^T
        float s[2][8][4];
        #pragma unroll
        for (int m = 0; m < 2; m++)
            #pragma unroll
            for (int j = 0; j < 8; j++)
                #pragma unroll
                for (int q = 0; q < 4; q++) s[m][j][q] = 0.f;
        #pragma unroll
        for (int d0 = 0; d0 < 64; d0 += 16) {
            uint32_t a0[4], a1[4];
            LDSM_X4(a0[0], a0[1], a0[2], a0[3], aK0 + d0 * 2);
            LDSM_X4(a1[0], a1[1], a1[2], a1[3], aK1 + d0 * 2);
            #pragma unroll
            for (int mt2 = 0; mt2 < 4; mt2++) {
                uint32_t r0, r1, r2, r3;
                LDSM_X4(r0, r1, r2, r3, qb + mt2 * 16 * HSTR * 2 + d0 * 2);
                MMA_F16(s[0][2 * mt2],     a0, r0, r2);
                MMA_F16(s[0][2 * mt2 + 1], a0, r1, r3);
                MMA_F16(s[1][2 * mt2],     a1, r0, r2);
                MMA_F16(s[1][2 * mt2 + 1], a1, r1, r3);
            }
        }

        // ---- packed approx exp2 -> P fragments
        uint32_t ph[2][4][4];
        #pragma unroll
        for (int m = 0; m < 2; m++)
            #pragma unroll
            for (int t2 = 0; t2 < 4; t2++) {
                ph[m][t2][0] = ex2h2(h2pack(s[m][2 * t2][0],     s[m][2 * t2][1]));
                ph[m][t2][1] = ex2h2(h2pack(s[m][2 * t2][2],     s[m][2 * t2][3]));
                ph[m][t2][2] = ex2h2(h2pack(s[m][2 * t2 + 1][0], s[m][2 * t2 + 1][1]));
                ph[m][t2][3] = ex2h2(h2pack(s[m][2 * t2 + 1][2], s[m][2 * t2 + 1][3]));
            }

        // ---- O += P @ V ; row sums += P @ ones
        #pragma unroll
        for (int e2 = 0; e2 < 4; e2++) {
            #pragma unroll
            for (int dt2 = 0; dt2 < 4; dt2++) {
                uint32_t r0, r1, r2, r3;
                LDSM_X4T(r0, r1, r2, r3, vb + e2 * 16 * HSTR * 2 + dt2 * 16 * 2);
                MMA_F16(o[0][2 * dt2],     ph[0][e2], r0, r1);
                MMA_F16(o[0][2 * dt2 + 1], ph[0][e2], r2, r3);
                MMA_F16(o[1][2 * dt2],     ph[1][e2], r0, r1);
                MMA_F16(o[1][2 * dt2 + 1], ph[1][e2], r2, r3);
            }
            MMA_F16(osum[0], ph[0][e2], ONES_H2, ONES_H2);
            MMA_F16(osum[1], ph[1][e2], ONES_H2, ONES_H2);
        }
    }

    // ---- store UNNORMALIZED fp32 partials + rowsums for this split
    float* po = g_po + (size_t)blockIdx.z * NTOK * NDIM;
    float* ps = g_ps + (size_t)blockIdx.z * NTOK * NH;
    #pragma unroll
    for (int m = 0; m < 2; m++) {
        const int r0 = n0 + wid * 32 + m * 16 + pr;
        if ((lane & 3) == 0) {
            ps[(tb + r0) * NH + h]     = osum[m][0];
            ps[(tb + r0 + 8) * NH + h] = osum[m][2];
        }
        #pragma unroll
        for (int dt = 0; dt < 8; dt++) {
            const int col = h * 64 + dt * 8 + pc;
            *(float2*)(po + (tb + r0) * NDIM + col) =
                make_float2(o[m][dt][0], o[m][dt][1]);
            *(float2*)(po + (tb + r0 + 8) * NDIM + col) =
                make_float2(o[m][dt][2], o[m][dt][3]);
        }
    }
}

// ============================================================================
extern "C" void kernel_launch(void* const* d_in, const int* in_sizes, int n_in,
                              void* d_out, int out_size)
{
    const float* X     = (const float*)d_in[0];
    const float* W_qkv = (const float*)d_in[1];
    const float* W_out = (const float*)d_in[2];
    const float* b_out = (const float*)d_in[3];
    float* out = (float*)d_out;

    __half *xh_p, *qkvh_p, *wtqh_p, *wtoh_p;
    cudaGetSymbolAddress((void**)&xh_p, g_xh);
    cudaGetSymbolAddress((void**)&qkvh_p, g_qkvh);
    cudaGetSymbolAddress((void**)&wtqh_p, g_wtqh);
    cudaGetSymbolAddress((void**)&wtoh_p, g_wtoh);

    cudaFuncSetAttribute(gemm_h,    cudaFuncAttributeMaxDynamicSharedMemorySize, GSMEM_H);
    cudaFuncSetAttribute(gemm_fuse, cudaFuncAttributeMaxDynamicSharedMemorySize, GSMEM_H);
    cudaFuncSetAttribute(attn_h,    cudaFuncAttributeMaxDynamicSharedMemorySize, ATT_SMEM);

    // prepasses: X -> half; weights -> K-major half
    tohalf<<<(NTOK * NDIM / 4) / 256, 256>>>(X, xh_p);
    ktrans_h<<<dim3(QKVN / 32, NDIM / 32), dim3(32, 8)>>>(W_qkv, wtqh_p, NDIM, QKVN);
    ktrans_h<<<dim3(NDIM / 32, NDIM / 32), dim3(32, 8)>>>(W_out, wtoh_p, NDIM, NDIM);

    // 1) QKV projection (fp16 mma), emits half, Q cols scaled by KSCALE
    gemm_h<<<dim3(QKVN / 128, NTOK / 128), 256, GSMEM_H>>>(
        xh_p, wtqh_p, qkvh_p, QKVN, NDIM);
    // 2) fused attention, split over m (2 splits); partials in g_po/g_ps
    attn_h<<<dim3(NN / 128, NB * NH, NSPLIT), 128, ATT_SMEM>>>();
    // 3) output projection + bias with fused split-combine on A
    gemm_fuse<<<dim3(NDIM / 128, NTOK / 128), 256, GSMEM_H>>>(
        wtoh_p, out, b_out);
}

// round 16
// speedup vs baseline: 1.0497x; 1.0497x over previous
#include <cuda_runtime.h>
#include <cuda_fp16.h>
#include <math_constants.h>
#include <cstdint>

// Problem constants
#define NB   4
#define NN   2048
#define NDIM 512
#define NH   8
#define NDH  64
#define NTOK 8192
#define QKVN 1536
#define KSCALE 0.18033688011112042f   // 0.125 * log2(e), folded into Q

// Scratch (allocation-free rule: __device__ globals)
__device__ __half g_xh[(size_t)NTOK * NDIM];
__device__ __half g_qkvh[(size_t)NTOK * QKVN];
__device__ __half g_atth[(size_t)NTOK * NDIM];
__device__ __half g_wtqh[(size_t)QKVN * NDIM];
__device__ __half g_wtoh[(size_t)NDIM * NDIM];

// ============================================================================
// helpers
// ============================================================================
__device__ __forceinline__ uint32_t smem_u32(const void* p) {
    uint32_t a;
    asm("{ .reg .u64 t; cvta.to.shared.u64 t, %1; cvt.u32.u64 %0, t; }" : "=r"(a) : "l"(p));
    return a;
}
__device__ __forceinline__ uint32_t h2pack(float lo, float hi) {
    uint32_t r;
    asm("cvt.rn.f16x2.f32 %0, %1, %2;" : "=r"(r) : "f"(hi), "f"(lo));
    return r;
}
__device__ __forceinline__ uint32_t ex2h2(uint32_t x) {
    uint32_t r;
    asm("ex2.approx.f16x2 %0, %1;" : "=r"(r) : "r"(x));
    return r;
}

#define LDSM_X4(r0, r1, r2, r3, addr) \
    asm volatile("ldmatrix.sync.aligned.m8n8.x4.shared.b16 {%0,%1,%2,%3}, [%4];" \
                 : "=r"(r0), "=r"(r1), "=r"(r2), "=r"(r3) : "r"(addr))
#define LDSM_X4T(r0, r1, r2, r3, addr) \
    asm volatile("ldmatrix.sync.aligned.m8n8.x4.trans.shared.b16 {%0,%1,%2,%3}, [%4];" \
                 : "=r"(r0), "=r"(r1), "=r"(r2), "=r"(r3) : "r"(addr))

#define MMA_F16(c, a, bb0, bb1) \
    asm volatile("mma.sync.aligned.m16n8k16.row.col.f32.f16.f16.f32 " \
                 "{%0,%1,%2,%3}, {%4,%5,%6,%7}, {%8,%9}, {%0,%1,%2,%3};" \
                 : "+f"((c)[0]), "+f"((c)[1]), "+f"((c)[2]), "+f"((c)[3]) \
                 : "r"((a)[0]), "r"((a)[1]), "r"((a)[2]), "r"((a)[3]), "r"(bb0), "r"(bb1))

#define CP_ASYNC16(dst, src) \
    asm volatile("cp.async.cg.shared.global [%0], [%1], 16;" :: "r"(dst), "l"(src))
#define CP_COMMIT() asm volatile("cp.async.commit_group;" ::: "memory")
#define CP_WAIT0()  asm volatile("cp.async.wait_group 0;" ::: "memory")
#define CP_WAIT1()  asm volatile("cp.async.wait_group 1;" ::: "memory")

// ============================================================================
// prepasses
// ============================================================================
__global__ void tohalf(const float* __restrict__ S, __half* __restrict__ D)
{
    const int i = blockIdx.x * blockDim.x + threadIdx.x;
    float4 v = ((const float4*)S)[i];
    ((uint2*)D)[i] = make_uint2(h2pack(v.x, v.y), h2pack(v.z, v.w));
}

__global__ void ktrans_h(const float* __restrict__ S, __half* __restrict__ D, int R, int Cc)
{
    __shared__ float t[32][33];
    const int c0 = blockIdx.x * 32, r0 = blockIdx.y * 32;
    for (int i = threadIdx.y; i < 32; i += 8)
        t[i][threadIdx.x] = S[(size_t)(r0 + i) * Cc + c0 + threadIdx.x];
    __syncthreads();
    for (int i = threadIdx.y; i < 32; i += 8)
        D[(size_t)(c0 + i) * R + r0 + threadIdx.x] = __float2half_rn(t[threadIdx.x][i]);
}

// ============================================================================
// fp16 mma GEMM (R8/R14 best config): C[M,N] = A[M,K] @ Bt[N,K]^T.
// 128x128x64 tiles, 256 thr, 8 warps (4m x 2n), warp tile 32x64.
// 3-stage cp.async pipeline, one barrier per k-tile.
// ============================================================================
#define HSTR 72
#define HBUF (128 * HSTR)
#define GSTG (HBUF * 2)                   // 18432 bytes / operand-stage
#define GSMEM_H (6 * GSTG)                // 110592 bytes

template<bool TO_HALF>
__global__ __launch_bounds__(256) void gemm_h(
    const __half* __restrict__ A, const __half* __restrict__ Bt,
    void* __restrict__ Cout, const float* __restrict__ bias,
    int Nfull, int K)
{
    extern __shared__ __half gs[];
    const int tid = threadIdx.x, lane = tid & 31, wid = tid >> 5;
    const int wm = (wid & 3) * 32, wn = (wid >> 2) * 64;
    const int row0 = blockIdx.y * 128, col0 = blockIdx.x * 128;
    const uint32_t sb = smem_u32(gs);

    const int lrow = lane & 15, lko = (lane >> 4) * 8;
    const uint32_t offA = (uint32_t)(((wm + lrow) * HSTR + lko) * 2);
    const uint32_t offB = (uint32_t)(((wn + lrow) * HSTR + lko) * 2);

    float c[2][8][4];
    #pragma unroll
    for (int i = 0; i < 2; i++)
        #pragma unroll
        for (int j = 0; j < 8; j++)
            #pragma unroll
            for (int q = 0; q < 4; q++) c[i][j][q] = 0.f;

    const int grow = tid >> 1, gc8 = (tid & 1) * 4;
    const __half* Ag = A + (size_t)(row0 + grow) * K + gc8 * 8;
    const __half* Bg = Bt + (size_t)(col0 + grow) * K + gc8 * 8;
    const uint32_t dA = sb + (uint32_t)((grow * HSTR + gc8 * 8) * 2);
    const uint32_t dB = sb + 3 * GSTG + (uint32_t)((grow * HSTR + gc8 * 8) * 2);

    const int KT = K / 64;
    #pragma unroll
    for (int pf = 0; pf < 2; pf++) {
        #pragma unroll
        for (int i = 0; i < 4; i++) {
            CP_ASYNC16(dA + pf * GSTG + i * 16, Ag + pf * 64 + i * 8);
            CP_ASYNC16(dB + pf * GSTG + i * 16, Bg + pf * 64 + i * 8);
        }
        CP_COMMIT();
    }

    for (int kt = 0; kt < KT; kt++) {
        if (kt + 1 < KT) CP_WAIT1(); else CP_WAIT0();
        __syncthreads();
        if (kt + 2 < KT) {
            const int st = (kt + 2) % 3;
            #pragma unroll
            for (int i = 0; i < 4; i++) {
                CP_ASYNC16(dA + st * GSTG + i * 16, Ag + (kt + 2) * 64 + i * 8);
                CP_ASYNC16(dB + st * GSTG + i * 16, Bg + (kt + 2) * 64 + i * 8);
            }
            CP_COMMIT();
        }
        const uint32_t aBase = sb + (kt % 3) * GSTG;
        const uint32_t bBase = sb + 3 * GSTG + (kt % 3) * GSTG;
        #pragma unroll
        for (int k0 = 0; k0 < 64; k0 += 16) {
            uint32_t a[2][4];
            #pragma unroll
            for (int mt = 0; mt < 2; mt++)
                LDSM_X4(a[mt][0], a[mt][1], a[mt][2], a[mt][3],
                        aBase + offA + mt * 16 * HSTR * 2 + k0 * 2);
            #pragma unroll
            for (int nt2 = 0; nt2 < 4; nt2++) {
                uint32_t r0, r1, r2, r3;
                LDSM_X4(r0, r1, r2, r3, bBase + offB + nt2 * 16 * HSTR * 2 + k0 * 2);
                MMA_F16(c[0][2 * nt2],     a[0], r0, r2);
                MMA_F16(c[0][2 * nt2 + 1], a[0], r1, r3);
                MMA_F16(c[1][2 * nt2],     a[1], r0, r2);
                MMA_F16(c[1][2 * nt2 + 1], a[1], r1, r3);
            }
        }
    }

    const int r0l = lane >> 2, q2 = (lane & 3) * 2;
    if (TO_HALF) {
        const float sc = (col0 < NDIM) ? KSCALE : 1.0f;   // scale Q region
        __half* C = (__half*)Cout;
        #pragma unroll
        for (int mt = 0; mt < 2; mt++)
            #pragma unroll
            for (int nt = 0; nt < 8; nt++) {
                const int row = row0 + wm + mt * 16 + r0l;
                const int col = col0 + wn + nt * 8 + q2;
                *(uint32_t*)(C + (size_t)row * Nfull + col) =
                    h2pack(c[mt][nt][0] * sc, c[mt][nt][1] * sc);
                *(uint32_t*)(C + (size_t)(row + 8) * Nfull + col) =
                    h2pack(c[mt][nt][2] * sc, c[mt][nt][3] * sc);
            }
    } else {
        float* C = (float*)Cout;
        #pragma unroll
        for (int mt = 0; mt < 2; mt++)
            #pragma unroll
            for (int nt = 0; nt < 8; nt++) {
                const int row = row0 + wm + mt * 16 + r0l;
                const int col = col0 + wn + nt * 8 + q2;
                float2 bb = *(const float2*)(bias + col);
                *(float2*)(C + (size_t)row * Nfull + col) =
                    make_float2(c[mt][nt][0] + bb.x, c[mt][nt][1] + bb.y);
                *(float2*)(C + (size_t)(row + 8) * Nfull + col) =
                    make_float2(c[mt][nt][2] + bb.x, c[mt][nt][3] + bb.y);
            }
    }
}

// ============================================================================
// fp16 mma flash attention, 64-ROW CTAs (no split, no partials):
// each CTA owns 64 n-rows of one (b,h) and the FULL m-loop (32 iters),
// writing final normalized half output directly. 128 thr = 4 warps x 16-row
// bands; K A-fragments hoisted (loop-invariant). ex2.approx.f16x2 softmax,
// ones-column MMA row sums. 3-stage Q/V cp.async pipeline.
// smem halves: Ks[64][72] | Qs[3][64][72] | Vs[3][64][72]  (64512 bytes)
// ============================================================================
#define KS_H 0
#define QVBUF 4608
#define QS_H 4608
#define VS_H (QS_H + 3 * QVBUF)           // 18432
#define ATT_SMEM ((VS_H + 3 * QVBUF) * 2) // 64512 bytes
#define NT (NN / 64)                      // 32 iterations
#define ONES_H2 0x3C003C00u

__global__ __launch_bounds__(128, 3) void attn_h()
{
    extern __shared__ __half sh[];
    const int tid = threadIdx.x, lane = tid & 31, wid = tid >> 5;
    const int bh = blockIdx.y, b = bh >> 3, h = bh & 7;
    const int n0 = blockIdx.x * 64;
    const size_t tb = (size_t)b * NN;
    const int qoff = h * 64, koff = NDIM + h * 64, voff = 2 * NDIM + h * 64;
    const uint32_t sb = smem_u32(sh);

    // K band: 64 rows, 2 threads/row, 4x16B chunks each (group 0)
    {
        const int kr = tid >> 1, kc = (tid & 1) * 4;
        const __half* src = g_qkvh + (tb + n0 + kr) * QKVN + koff + kc * 8;
        const uint32_t dst = sb + (uint32_t)((KS_H + kr * HSTR + kc * 8) * 2);
        #pragma unroll
        for (int i = 0; i < 4; i++)
            CP_ASYNC16(dst + i * 16, src + i * 8);
    }
    // Q/V tiles 0,1 (2 threads per row, 4 chunks each); K joins group 0
    const int qr = tid >> 1, qc8 = (tid & 1) * 4;
    #pragma unroll
    for (int pf = 0; pf < 2; pf++) {
        const size_t rb = tb + pf * 64 + qr;
        #pragma unroll
        for (int i = 0; i < 4; i++) {
            CP_ASYNC16(sb + (uint32_t)((QS_H + pf * QVBUF + qr * HSTR + (qc8 + i) * 8) * 2),
                       g_qkvh + rb * QKVN + qoff + (qc8 + i) * 8);
            CP_ASYNC16(sb + (uint32_t)((VS_H + pf * QVBUF + qr * HSTR + (qc8 + i) * 8) * 2),
                       g_qkvh + rb * QKVN + voff + (qc8 + i) * 8);
        }
        CP_COMMIT();
    }

    float o[8][4];
    #pragma unroll
    for (int j = 0; j < 8; j++)
        #pragma unroll
        for (int q = 0; q < 4; q++) o[j][q] = 0.f;
    float osum[4] = {0.f, 0.f, 0.f, 0.f};

    const int lrow = lane & 15, lko = (lane >> 4) * 8;
    const uint32_t aK = sb + (uint32_t)(((wid * 16 + lrow) * HSTR + lko) * 2);
    const int vrow = ((lane >> 3) & 1) * 8 + (lane & 7);
    const int pr = lane >> 2, pc = (lane & 3) * 2;

    // ---- hoist K A-fragments (loop-invariant): 4 k16-steps
    uint32_t kf[4][4];
    CP_WAIT1();                // group 0 (K + QV0) complete
    __syncthreads();
    #pragma unroll
    for (int d = 0; d < 4; d++)
        LDSM_X4(kf[d][0], kf[d][1], kf[d][2], kf[d][3], aK + d * 32);

    for (int it = 0; it < NT; it++) {
        if (it + 1 < NT) CP_WAIT1(); else CP_WAIT0();
        __syncthreads();
        if (it + 2 < NT) {
            const int st = (it + 2) % 3;
            const size_t rb = tb + (it + 2) * 64 + qr;
            #pragma unroll
            for (int i = 0; i < 4; i++) {
                CP_ASYNC16(sb + (uint32_t)((QS_H + st * QVBUF + qr * HSTR + (qc8 + i) * 8) * 2),
                           g_qkvh + rb * QKVN + qoff + (qc8 + i) * 8);
                CP_ASYNC16(sb + (uint32_t)((VS_H + st * QVBUF + qr * HSTR + (qc8 + i) * 8) * 2),
                           g_qkvh + rb * QKVN + voff + (qc8 + i) * 8);
            }
            CP_COMMIT();
        }
        const int rs = it % 3;
        const uint32_t qb = sb + (uint32_t)((QS_H + rs * QVBUF + lrow * HSTR + lko) * 2);
        const uint32_t vb = sb + (uint32_t)((VS_H + rs * QVBUF + vrow * HSTR + lko) * 2);

        // ---- S = K . Q^T  (one m16 band x eight n8 tiles, K from regs)
        float s[8][4];
        #pragma unroll
        for (int j = 0; j < 8; j++)
            #pragma unroll
            for (int q = 0; q < 4; q++) s[j][q] = 0.f;
        #pragma unroll
        for (int d = 0; d < 4; d++) {
            #pragma unroll
            for (int mt2 = 0; mt2 < 4; mt2++) {
                uint32_t r0, r1, r2, r3;
                LDSM_X4(r0, r1, r2, r3, qb + mt2 * 16 * HSTR * 2 + d * 32);
                MMA_F16(s[2 * mt2],     kf[d], r0, r2);
                MMA_F16(s[2 * mt2 + 1], kf[d], r1, r3);
            }
        }

        // ---- packed approx exp2 -> P fragments
        uint32_t ph[4][4];
        #pragma unroll
        for (int t2 = 0; t2 < 4; t2++) {
            ph[t2][0] = ex2h2(h2pack(s[2 * t2][0],     s[2 * t2][1]));
            ph[t2][1] = ex2h2(h2pack(s[2 * t2][2],     s[2 * t2][3]));
            ph[t2][2] = ex2h2(h2pack(s[2 * t2 + 1][0], s[2 * t2 + 1][1]));
            ph[t2][3] = ex2h2(h2pack(s[2 * t2 + 1][2], s[2 * t2 + 1][3]));
        }

        // ---- O += P @ V ; row sums += P @ ones (same fp16 P, f32 accum)
        #pragma unroll
        for (int e2 = 0; e2 < 4; e2++) {
            #pragma unroll
            for (int dt2 = 0; dt2 < 4; dt2++) {
                uint32_t r0, r1, r2, r3;
                LDSM_X4T(r0, r1, r2, r3, vb + e2 * 16 * HSTR * 2 + dt2 * 32);
                MMA_F16(o[2 * dt2],     ph[e2], r0, r1);
                MMA_F16(o[2 * dt2 + 1], ph[e2], r2, r3);
            }
            MMA_F16(osum, ph[e2], ONES_H2, ONES_H2);
        }
    }

    // osum[0] = row pr full sum, osum[2] = row pr+8 (k-reduced inside MMA)
    const float i0 = __fdividef(1.f, osum[0]);
    const float i1 = __fdividef(1.f, osum[2]);
    #pragma unroll
    for (int dt = 0; dt < 8; dt++) {
        const int row = n0 + wid * 16 + pr;
        const int col = h * 64 + dt * 8 + pc;
        *(uint32_t*)(g_atth + (tb + row) * NDIM + col) =
            h2pack(o[dt][0] * i0, o[dt][1] * i0);
        *(uint32_t*)(g_atth + (tb + row + 8) * NDIM + col) =
            h2pack(o[dt][2] * i1, o[dt][3] * i1);
    }
}

// ============================================================================
extern "C" void kernel_launch(void* const* d_in, const int* in_sizes, int n_in,
                              void* d_out, int out_size)
{
    const float* X     = (const float*)d_in[0];
    const float* W_qkv = (const float*)d_in[1];
    const float* W_out = (const float*)d_in[2];
    const float* b_out = (const float*)d_in[3];
    float* out = (float*)d_out;

    __half *xh_p, *qkvh_p, *atth_p, *wtqh_p, *wtoh_p;
    cudaGetSymbolAddress((void**)&xh_p, g_xh);
    cudaGetSymbolAddress((void**)&qkvh_p, g_qkvh);
    cudaGetSymbolAddress((void**)&atth_p, g_atth);
    cudaGetSymbolAddress((void**)&wtqh_p, g_wtqh);
    cudaGetSymbolAddress((void**)&wtoh_p, g_wtoh);

    cudaFuncSetAttribute(gemm_h<true>,  cudaFuncAttributeMaxDynamicSharedMemorySize, GSMEM_H);
    cudaFuncSetAttribute(gemm_h<false>, cudaFuncAttributeMaxDynamicSharedMemorySize, GSMEM_H);
    cudaFuncSetAttribute(attn_h, cudaFuncAttributeMaxDynamicSharedMemorySize, ATT_SMEM);

    // prepasses: X -> half; weights -> K-major half
    tohalf<<<(NTOK * NDIM / 4) / 256, 256>>>(X, xh_p);
    ktrans_h<<<dim3(QKVN / 32, NDIM / 32), dim3(32, 8)>>>(W_qkv, wtqh_p, NDIM, QKVN);
    ktrans_h<<<dim3(NDIM / 32, NDIM / 32), dim3(32, 8)>>>(W_out, wtoh_p, NDIM, NDIM);

    // 1) QKV projection (fp16 mma), emits half, Q cols scaled by KSCALE
    gemm_h<true><<<dim3(QKVN / 128, NTOK / 128), 256, GSMEM_H>>>(
        xh_p, wtqh_p, qkvh_p, nullptr, QKVN, NDIM);
    // 2) fused attention: 64-row CTAs, full m-loop, direct half output
    attn_h<<<dim3(NN / 64, NB * NH), 128, ATT_SMEM>>>();
    // 3) output projection + bias (fp16 mma, f32 out)
    gemm_h<false><<<dim3(NDIM / 128, NTOK / 128), 256, GSMEM_H>>>(
        atth_p, wtoh_p, out, b_out, NDIM, NDIM);
}

// round 17
// speedup vs baseline: 1.2082x; 1.1510x over previous
#include <cuda_runtime.h>
#include <cuda_fp16.h>
#include <math_constants.h>
#include <cstdint>

// Problem constants
#define NB   4
#define NN   2048
#define NDIM 512
#define NH   8
#define NDH  64
#define NTOK 8192
#define QKVN 1536
#define KSCALE 0.18033688011112042f   // 0.125 * log2(e), folded into Q
#define NSPLIT 2
#define MSPL (NN / NSPLIT)            // 1024 m-columns per split

// Scratch (allocation-free rule: __device__ globals)
__device__ __half g_xh[(size_t)NTOK * NDIM];
__device__ __half g_qkvh[(size_t)NTOK * QKVN];
__device__ __half g_atth[(size_t)NTOK * NDIM];
__device__ __half g_wtqh[(size_t)QKVN * NDIM];
__device__ __half g_wtoh[(size_t)NDIM * NDIM];
__device__ __half g_poh[(size_t)NSPLIT * NTOK * NDIM];  // partial O (unnormalized, fp16)
__device__ float  g_ps[(size_t)NSPLIT * NTOK * NH];     // partial row sums (fp32)

// ============================================================================
// helpers
// ============================================================================
__device__ __forceinline__ uint32_t smem_u32(const void* p) {
    uint32_t a;
    asm("{ .reg .u64 t; cvta.to.shared.u64 t, %1; cvt.u32.u64 %0, t; }" : "=r"(a) : "l"(p));
    return a;
}
__device__ __forceinline__ uint32_t h2pack(float lo, float hi) {
    uint32_t r;
    asm("cvt.rn.f16x2.f32 %0, %1, %2;" : "=r"(r) : "f"(hi), "f"(lo));
    return r;
}
__device__ __forceinline__ uint32_t ex2h2(uint32_t x) {
    uint32_t r;
    asm("ex2.approx.f16x2 %0, %1;" : "=r"(r) : "r"(x));
    return r;
}

#define LDSM_X4(r0, r1, r2, r3, addr) \
    asm volatile("ldmatrix.sync.aligned.m8n8.x4.shared.b16 {%0,%1,%2,%3}, [%4];" \
                 : "=r"(r0), "=r"(r1), "=r"(r2), "=r"(r3) : "r"(addr))
#define LDSM_X4T(r0, r1, r2, r3, addr) \
    asm volatile("ldmatrix.sync.aligned.m8n8.x4.trans.shared.b16 {%0,%1,%2,%3}, [%4];" \
                 : "=r"(r0), "=r"(r1), "=r"(r2), "=r"(r3) : "r"(addr))

#define MMA_F16(c, a, bb0, bb1) \
    asm volatile("mma.sync.aligned.m16n8k16.row.col.f32.f16.f16.f32 " \
                 "{%0,%1,%2,%3}, {%4,%5,%6,%7}, {%8,%9}, {%0,%1,%2,%3};" \
                 : "+f"((c)[0]), "+f"((c)[1]), "+f"((c)[2]), "+f"((c)[3]) \
                 : "r"((a)[0]), "r"((a)[1]), "r"((a)[2]), "r"((a)[3]), "r"(bb0), "r"(bb1))

#define CP_ASYNC16(dst, src) \
    asm volatile("cp.async.cg.shared.global [%0], [%1], 16;" :: "r"(dst), "l"(src))
#define CP_COMMIT() asm volatile("cp.async.commit_group;" ::: "memory")
#define CP_WAIT0()  asm volatile("cp.async.wait_group 0;" ::: "memory")
#define CP_WAIT1()  asm volatile("cp.async.wait_group 1;" ::: "memory")

// ============================================================================
// fused prepass: X -> half  |  W_qkv -> K-major half  |  W_out -> K-major half
// block-range dispatch, one launch.
// ============================================================================
#define PREP_TH (NTOK * NDIM / 4 / 256)          // 4096 blocks for tohalf
#define PREP_WQ (QKVN / 32 * (NDIM / 32))        // 768 blocks (48 x 16)
#define PREP_WO (NDIM / 32 * (NDIM / 32))        // 256 blocks (16 x 16)

__global__ void prep(const float* __restrict__ X,
                     const float* __restrict__ Wq,
                     const float* __restrict__ Wo)
{
    __shared__ float t[32][33];
    const int bid = blockIdx.x, tid = threadIdx.x;
    if (bid < PREP_TH) {
        const int i = bid * 256 + tid;
        float4 v = ((const float4*)X)[i];
        ((uint2*)g_xh)[i] = make_uint2(h2pack(v.x, v.y), h2pack(v.z, v.w));
        return;
    }
    const float* S;
    __half* D;
    int c0, r0, R, Cc;
    if (bid < PREP_TH + PREP_WQ) {
        const int tb = bid - PREP_TH;
        c0 = (tb % (QKVN / 32)) * 32; r0 = (tb / (QKVN / 32)) * 32;
        S = Wq; D = g_wtqh; R = NDIM; Cc = QKVN;
    } else {
        const int tb = bid - PREP_TH - PREP_WQ;
        c0 = (tb % (NDIM / 32)) * 32; r0 = (tb / (NDIM / 32)) * 32;
        S = Wo; D = g_wtoh; R = NDIM; Cc = NDIM;
    }
    const int tx = tid & 31, ty = tid >> 5;
    for (int i = ty; i < 32; i += 8)
        t[i][tx] = S[(size_t)(r0 + i) * Cc + c0 + tx];
    __syncthreads();
    for (int i = ty; i < 32; i += 8)
        D[(size_t)(c0 + i) * R + r0 + tx] = __float2half_rn(t[tx][i]);
}

// ============================================================================
// fp16 mma GEMM (R8/R14 best config): C[M,N] = A[M,K] @ Bt[N,K]^T.
// 128x128x64 tiles, 256 thr, 8 warps (4m x 2n), warp tile 32x64.
// 3-stage cp.async pipeline, one barrier per k-tile.
// ============================================================================
#define HSTR 72
#define HBUF (128 * HSTR)
#define GSTG (HBUF * 2)                   // 18432 bytes / operand-stage
#define GSMEM_H (6 * GSTG)                // 110592 bytes

template<bool TO_HALF>
__global__ __launch_bounds__(256) void gemm_h(
    const __half* __restrict__ A, const __half* __restrict__ Bt,
    void* __restrict__ Cout, const float* __restrict__ bias,
    int Nfull, int K)
{
    extern __shared__ __half gs[];
    const int tid = threadIdx.x, lane = tid & 31, wid = tid >> 5;
    const int wm = (wid & 3) * 32, wn = (wid >> 2) * 64;
    const int row0 = blockIdx.y * 128, col0 = blockIdx.x * 128;
    const uint32_t sb = smem_u32(gs);

    const int lrow = lane & 15, lko = (lane >> 4) * 8;
    const uint32_t offA = (uint32_t)(((wm + lrow) * HSTR + lko) * 2);
    const uint32_t offB = (uint32_t)(((wn + lrow) * HSTR + lko) * 2);

    float c[2][8][4];
    #pragma unroll
    for (int i = 0; i < 2; i++)
        #pragma unroll
        for (int j = 0; j < 8; j++)
            #pragma unroll
            for (int q = 0; q < 4; q++) c[i][j][q] = 0.f;

    const int grow = tid >> 1, gc8 = (tid & 1) * 4;
    const __half* Ag = A + (size_t)(row0 + grow) * K + gc8 * 8;
    const __half* Bg = Bt + (size_t)(col0 + grow) * K + gc8 * 8;
    const uint32_t dA = sb + (uint32_t)((grow * HSTR + gc8 * 8) * 2);
    const uint32_t dB = sb + 3 * GSTG + (uint32_t)((grow * HSTR + gc8 * 8) * 2);

    const int KT = K / 64;
    #pragma unroll
    for (int pf = 0; pf < 2; pf++) {
        #pragma unroll
        for (int i = 0; i < 4; i++) {
            CP_ASYNC16(dA + pf * GSTG + i * 16, Ag + pf * 64 + i * 8);
            CP_ASYNC16(dB + pf * GSTG + i * 16, Bg + pf * 64 + i * 8);
        }
        CP_COMMIT();
    }

    for (int kt = 0; kt < KT; kt++) {
        if (kt + 1 < KT) CP_WAIT1(); else CP_WAIT0();
        __syncthreads();
        if (kt + 2 < KT) {
            const int st = (kt + 2) % 3;
            #pragma unroll
            for (int i = 0; i < 4; i++) {
                CP_ASYNC16(dA + st * GSTG + i * 16, Ag + (kt + 2) * 64 + i * 8);
                CP_ASYNC16(dB + st * GSTG + i * 16, Bg + (kt + 2) * 64 + i * 8);
            }
            CP_COMMIT();
        }
        const uint32_t aBase = sb + (kt % 3) * GSTG;
        const uint32_t bBase = sb + 3 * GSTG + (kt % 3) * GSTG;
        #pragma unroll
        for (int k0 = 0; k0 < 64; k0 += 16) {
            uint32_t a[2][4];
            #pragma unroll
            for (int mt = 0; mt < 2; mt++)
                LDSM_X4(a[mt][0], a[mt][1], a[mt][2], a[mt][3],
                        aBase + offA + mt * 16 * HSTR * 2 + k0 * 2);
            #pragma unroll
            for (int nt2 = 0; nt2 < 4; nt2++) {
                uint32_t r0, r1, r2, r3;
                LDSM_X4(r0, r1, r2, r3, bBase + offB + nt2 * 16 * HSTR * 2 + k0 * 2);
                MMA_F16(c[0][2 * nt2],     a[0], r0, r2);
                MMA_F16(c[0][2 * nt2 + 1], a[0], r1, r3);
                MMA_F16(c[1][2 * nt2],     a[1], r0, r2);
                MMA_F16(c[1][2 * nt2 + 1], a[1], r1, r3);
            }
        }
    }

    const int r0l = lane >> 2, q2 = (lane & 3) * 2;
    if (TO_HALF) {
        const float sc = (col0 < NDIM) ? KSCALE : 1.0f;   // scale Q region
        __half* C = (__half*)Cout;
        #pragma unroll
        for (int mt = 0; mt < 2; mt++)
            #pragma unroll
            for (int nt = 0; nt < 8; nt++) {
                const int row = row0 + wm + mt * 16 + r0l;
                const int col = col0 + wn + nt * 8 + q2;
                *(uint32_t*)(C + (size_t)row * Nfull + col) =
                    h2pack(c[mt][nt][0] * sc, c[mt][nt][1] * sc);
                *(uint32_t*)(C + (size_t)(row + 8) * Nfull + col) =
                    h2pack(c[mt][nt][2] * sc, c[mt][nt][3] * sc);
            }
    } else {
        float* C = (float*)Cout;
        #pragma unroll
        for (int mt = 0; mt < 2; mt++)
            #pragma unroll
            for (int nt = 0; nt < 8; nt++) {
                const int row = row0 + wm + mt * 16 + r0l;
                const int col = col0 + wn + nt * 8 + q2;
                float2 bb = *(const float2*)(bias + col);
                *(float2*)(C + (size_t)row * Nfull + col) =
                    make_float2(c[mt][nt][0] + bb.x, c[mt][nt][1] + bb.y);
                *(float2*)(C + (size_t)(row + 8) * Nfull + col) =
                    make_float2(c[mt][nt][2] + bb.x, c[mt][nt][3] + bb.y);
            }
    }
}

// ============================================================================
// fp16 mma flash attention, SPLIT-M (2 splits): each CTA handles a 1024-wide
// m-slice (16 iterations), writes unnormalized fp16 partial O + fp32 rowsums.
// CTA: 128 thr (4 warps x 32-row bands), 128 n-rows. ex2.approx.f16x2
// softmax, ones-column MMA row sums. 3-stage Q/V cp.async pipeline.
// smem halves: Ks[128][72] | Qs[3][64][72] | Vs[3][64][72]  (73728 bytes)
// ============================================================================
#define KS_H 0
#define QS_H 9216
#define QVBUF 4608
#define VS_H (QS_H + 3 * QVBUF)
#define ATT_SMEM ((VS_H + 3 * QVBUF) * 2)
#define NTS (MSPL / 64)                   // 16 iterations per split
#define ONES_H2 0x3C003C00u

__global__ __launch_bounds__(128, 3) void attn_h()
{
    extern __shared__ __half sh[];
    const int tid = threadIdx.x, lane = tid & 31, wid = tid >> 5;
    const int bh = blockIdx.y, b = bh >> 3, h = bh & 7;
    const int n0 = blockIdx.x * 128;
    const int m0b = blockIdx.z * MSPL;
    const size_t tb = (size_t)b * NN;
    const int qoff = h * 64, koff = NDIM + h * 64, voff = 2 * NDIM + h * 64;
    const uint32_t sb = smem_u32(sh);

    // K band: one row per thread (128 threads), 8x16B chunks (group 0)
    {
        const __half* src = g_qkvh + (tb + n0 + tid) * QKVN + koff;
        const uint32_t dst = sb + (uint32_t)((KS_H + tid * HSTR) * 2);
        #pragma unroll
        for (int i = 0; i < 8; i++)
            CP_ASYNC16(dst + i * 16, src + i * 8);
    }
    // Q/V tiles 0,1 of this split (2 threads per row, 4 chunks each)
    const int qr = tid >> 1, qc8 = (tid & 1) * 4;
    #pragma unroll
    for (int pf = 0; pf < 2; pf++) {
        const size_t rb = tb + m0b + pf * 64 + qr;
        #pragma unroll
        for (int i = 0; i < 4; i++) {
            CP_ASYNC16(sb + (uint32_t)((QS_H + pf * QVBUF + qr * HSTR + (qc8 + i) * 8) * 2),
                       g_qkvh + rb * QKVN + qoff + (qc8 + i) * 8);
            CP_ASYNC16(sb + (uint32_t)((VS_H + pf * QVBUF + qr * HSTR + (qc8 + i) * 8) * 2),
                       g_qkvh + rb * QKVN + voff + (qc8 + i) * 8);
        }
        CP_COMMIT();
    }

    float o[2][8][4];
    #pragma unroll
    for (int m = 0; m < 2; m++)
        #pragma unroll
        for (int j = 0; j < 8; j++)
            #pragma unroll
            for (int q = 0; q < 4; q++) o[m][j][q] = 0.f;
    float osum[2][4];
    #pragma unroll
    for (int m = 0; m < 2; m++)
        #pragma unroll
        for (int q = 0; q < 4; q++) osum[m][q] = 0.f;

    const int lrow = lane & 15, lko = (lane >> 4) * 8;
    const uint32_t aK0 = sb + (uint32_t)(((wid * 32 + lrow) * HSTR + lko) * 2);
    const uint32_t aK1 = aK0 + 16 * HSTR * 2;
    const int vrow = ((lane >> 3) & 1) * 8 + (lane & 7);
    const int pr = lane >> 2, pc = (lane & 3) * 2;

    for (int it = 0; it < NTS; it++) {
        if (it + 1 < NTS) CP_WAIT1(); else CP_WAIT0();
        __syncthreads();
        if (it + 2 < NTS) {
            const int st = (it + 2) % 3;
            const size_t rb = tb + m0b + (it + 2) * 64 + qr;
            #pragma unroll
            for (int i = 0; i < 4; i++) {
                CP_ASYNC16(sb + (uint32_t)((QS_H + st * QVBUF + qr * HSTR + (qc8 + i) * 8) * 2),
                           g_qkvh + rb * QKVN + qoff + (qc8 + i) * 8);
                CP_ASYNC16(sb + (uint32_t)((VS_H + st * QVBUF + qr * HSTR + (qc8 + i) * 8) * 2),
                           g_qkvh + rb * QKVN + voff + (qc8 + i) * 8);
            }
            CP_COMMIT();
        }
        const int rs = it % 3;
        const uint32_t qb = sb + (uint32_t)((QS_H + rs * QVBUF + lrow * HSTR + lko) * 2);
        const uint32_t vb = sb + (uint32_t)((VS_H + rs * QVBUF + vrow * HSTR + lko) * 2);

        // ---- S = K . Q^T
        float s[2][8][4];
        #pragma unroll
        for (int m = 0; m < 2; m++)
            #pragma unroll
            for (int j = 0; j < 8; j++)
                #pragma unroll
                for (int q = 0; q < 4; q++) s[m][j][q] = 0.f;
        #pragma unroll
        for (int d0 = 0; d0 < 64; d0 += 16) {
            uint32_t a0[4], a1[4];
            LDSM_X4(a0[0], a0[1], a0[2], a0[3], aK0 + d0 * 2);
            LDSM_X4(a1[0], a1[1], a1[2], a1[3], aK1 + d0 * 2);
            #pragma unroll
            for (int mt2 = 0; mt2 < 4; mt2++) {
                uint32_t r0, r1, r2, r3;
                LDSM_X4(r0, r1, r2, r3, qb + mt2 * 16 * HSTR * 2 + d0 * 2);
                MMA_F16(s[0][2 * mt2],     a0, r0, r2);
                MMA_F16(s[0][2 * mt2 + 1], a0, r1, r3);
                MMA_F16(s[1][2 * mt2],     a1, r0, r2);
                MMA_F16(s[1][2 * mt2 + 1], a1, r1, r3);
            }
        }

        // ---- packed approx exp2 -> P fragments
        uint32_t ph[2][4][4];
        #pragma unroll
        for (int m = 0; m < 2; m++)
            #pragma unroll
            for (int t2 = 0; t2 < 4; t2++) {
                ph[m][t2][0] = ex2h2(h2pack(s[m][2 * t2][0],     s[m][2 * t2][1]));
                ph[m][t2][1] = ex2h2(h2pack(s[m][2 * t2][2],     s[m][2 * t2][3]));
                ph[m][t2][2] = ex2h2(h2pack(s[m][2 * t2 + 1][0], s[m][2 * t2 + 1][1]));
                ph[m][t2][3] = ex2h2(h2pack(s[m][2 * t2 + 1][2], s[m][2 * t2 + 1][3]));
            }

        // ---- O += P @ V ; row sums += P @ ones
        #pragma unroll
        for (int e2 = 0; e2 < 4; e2++) {
            #pragma unroll
            for (int dt2 = 0; dt2 < 4; dt2++) {
                uint32_t r0, r1, r2, r3;
                LDSM_X4T(r0, r1, r2, r3, vb + e2 * 16 * HSTR * 2 + dt2 * 16 * 2);
                MMA_F16(o[0][2 * dt2],     ph[0][e2], r0, r1);
                MMA_F16(o[0][2 * dt2 + 1], ph[0][e2], r2, r3);
                MMA_F16(o[1][2 * dt2],     ph[1][e2], r0, r1);
                MMA_F16(o[1][2 * dt2 + 1], ph[1][e2], r2, r3);
            }
            MMA_F16(osum[0], ph[0][e2], ONES_H2, ONES_H2);
            MMA_F16(osum[1], ph[1][e2], ONES_H2, ONES_H2);
        }
    }

    // ---- store UNNORMALIZED fp16 partials + fp32 rowsums for this split
    __half* po = g_poh + (size_t)blockIdx.z * NTOK * NDIM;
    float* ps = g_ps + (size_t)blockIdx.z * NTOK * NH;
    #pragma unroll
    for (int m = 0; m < 2; m++) {
        const int r0 = n0 + wid * 32 + m * 16 + pr;
        if ((lane & 3) == 0) {
            ps[(tb + r0) * NH + h]     = osum[m][0];
            ps[(tb + r0 + 8) * NH + h] = osum[m][2];
        }
        #pragma unroll
        for (int dt = 0; dt < 8; dt++) {
            const int col = h * 64 + dt * 8 + pc;
            *(uint32_t*)(po + (tb + r0) * NDIM + col) =
                h2pack(o[m][dt][0], o[m][dt][1]);
            *(uint32_t*)(po + (tb + r0 + 8) * NDIM + col) =
                h2pack(o[m][dt][2], o[m][dt][3]);
        }
    }
}

// ============================================================================
// split reduction: g_atth = (sum_splits g_poh) / (sum_splits g_ps), as half
// ============================================================================
__global__ void attn_reduce()
{
    const int i = blockIdx.x * 256 + threadIdx.x;   // over NTOK*NDIM/4
    const int e = i * 4;
    const int token = e >> 9;        // / NDIM
    const int h = (e & 511) >> 6;

    float ssum = 0.f;
    float4 acc = make_float4(0.f, 0.f, 0.f, 0.f);
    #pragma unroll
    for (int sp = 0; sp < NSPLIT; sp++) {
        ssum += g_ps[(size_t)sp * NTOK * NH + (size_t)token * NH + h];
        const __half2* v = (const __half2*)(g_poh + (size_t)sp * NTOK * NDIM + e);
        float2 lo = __half22float2(v[0]);
        float2 hi = __half22float2(v[1]);
        acc.x += lo.x; acc.y += lo.y; acc.z += hi.x; acc.w += hi.y;
    }
    const float inv = __fdividef(1.f, ssum);
    ((uint2*)g_atth)[i] = make_uint2(h2pack(acc.x * inv, acc.y * inv),
                                     h2pack(acc.z * inv, acc.w * inv));
}

// ============================================================================
extern "C" void kernel_launch(void* const* d_in, const int* in_sizes, int n_in,
                              void* d_out, int out_size)
{
    const float* X     = (const float*)d_in[0];
    const float* W_qkv = (const float*)d_in[1];
    const float* W_out = (const float*)d_in[2];
    const float* b_out = (const float*)d_in[3];
    float* out = (float*)d_out;

    __half *xh_p, *qkvh_p, *atth_p, *wtqh_p, *wtoh_p;
    cudaGetSymbolAddress((void**)&xh_p, g_xh);
    cudaGetSymbolAddress((void**)&qkvh_p, g_qkvh);
    cudaGetSymbolAddress((void**)&atth_p, g_atth);
    cudaGetSymbolAddress((void**)&wtqh_p, g_wtqh);
    cudaGetSymbolAddress((void**)&wtoh_p, g_wtoh);

    cudaFuncSetAttribute(gemm_h<true>,  cudaFuncAttributeMaxDynamicSharedMemorySize, GSMEM_H);
    cudaFuncSetAttribute(gemm_h<false>, cudaFuncAttributeMaxDynamicSharedMemorySize, GSMEM_H);
    cudaFuncSetAttribute(attn_h, cudaFuncAttributeMaxDynamicSharedMemorySize, ATT_SMEM);

    // fused prepass (X -> half; both weights -> K-major half), one launch
    prep<<<PREP_TH + PREP_WQ + PREP_WO, 256>>>(X, W_qkv, W_out);

    // 1) QKV projection (fp16 mma), emits half, Q cols scaled by KSCALE
    gemm_h<true><<<dim3(QKVN / 128, NTOK / 128), 256, GSMEM_H>>>(
        xh_p, wtqh_p, qkvh_p, nullptr, QKVN, NDIM);
    // 2) fused attention, split over m (2 splits) + exact combine
    attn_h<<<dim3(NN / 128, NB * NH, NSPLIT), 128, ATT_SMEM>>>();
    attn_reduce<<<(NTOK * NDIM / 4) / 256, 256>>>();
    // 3) output projection + bias (fp16 mma, f32 out)
    gemm_h<false><<<dim3(NDIM / 128, NTOK / 128), 256, GSMEM_H>>>(
        atth_p, wtoh_p, out, b_out, NDIM, NDIM);
}